// round 5
// baseline (speedup 1.0000x reference)
#include <cuda_runtime.h>
#include <cuda_bf16.h>

#define N_NODES 50000
#define E_EDGES 1000000
#define DIM     64
#define G_GRAPHS 512
#define O_DIM   16

// Scratch (__device__ globals; no allocation allowed)
__device__ float g_p   [N_NODES * DIM];     // projected (Wl) features
__device__ float g_xr  [N_NODES * DIM];     // root-path (Wr) features
__device__ float g_h1  [N_NODES * DIM];     // layer-1 output
__device__ float g_pool[G_GRAPHS * DIM];
__device__ int   g_counts[N_NODES];
__device__ int   g_rowptr[N_NODES + 1];
__device__ int   g_cursor[N_NODES];
__device__ int   g_esrc  [E_EDGES];

union F2U { unsigned long long u; float2 f; };

#define FMA2(d, a, b) \
    asm("fma.rn.f32x2 %0, %1, %2, %0;" : "+l"(d) : "l"(a), "l"(b))

// ---------------------------------------------------------------------------
// zero counts + pool
// ---------------------------------------------------------------------------
__global__ void zero2_kernel(int* __restrict__ counts, float* __restrict__ pool) {
    int i = blockIdx.x * blockDim.x + threadIdx.x;
    if (i < N_NODES) counts[i] = 0;
    if (i < G_GRAPHS * DIM) pool[i] = 0.f;
}

// ---------------------------------------------------------------------------
// histogram of dst: 8 edges / thread, loads hoisted ahead of atomics
// ---------------------------------------------------------------------------
__global__ void hist_kernel(const int* __restrict__ dst, int* __restrict__ counts) {
    int base = (blockIdx.x * blockDim.x + threadIdx.x) * 8;
    if (base + 8 <= E_EDGES) {
        int d[8];
        #pragma unroll
        for (int j = 0; j < 8; j++) d[j] = __ldg(&dst[base + j]);
        #pragma unroll
        for (int j = 0; j < 8; j++) atomicAdd(&counts[d[j]], 1);
    } else {
        for (int e = base; e < E_EDGES; e++) atomicAdd(&counts[__ldg(&dst[e])], 1);
    }
}

// ---------------------------------------------------------------------------
// exclusive scan of counts -> rowptr (+ cursor); warp-shuffle based
// ---------------------------------------------------------------------------
__global__ __launch_bounds__(1024) void scan_kernel(const int* __restrict__ counts,
                                                    int* __restrict__ rowptr,
                                                    int* __restrict__ cursor) {
    __shared__ int warpsum[32];
    const int CH = 49;
    int t = threadIdx.x;
    int base = t * CH;
    int lane = t & 31, wid = t >> 5;

    int s = 0;
    #pragma unroll 7
    for (int i = 0; i < CH; i++) {
        int idx = base + i;
        if (idx < N_NODES) s += __ldg(&counts[idx]);
    }
    int v = s;
    #pragma unroll
    for (int off = 1; off < 32; off <<= 1) {
        int u = __shfl_up_sync(0xffffffffu, v, off);
        if (lane >= off) v += u;
    }
    if (lane == 31) warpsum[wid] = v;
    __syncthreads();
    if (wid == 0) {
        int w = warpsum[lane];
        #pragma unroll
        for (int off = 1; off < 32; off <<= 1) {
            int u = __shfl_up_sync(0xffffffffu, w, off);
            if (lane >= off) w += u;
        }
        warpsum[lane] = w;
    }
    __syncthreads();

    int run = v - s + (wid > 0 ? warpsum[wid - 1] : 0);
    #pragma unroll 7
    for (int i = 0; i < CH; i++) {
        int idx = base + i;
        if (idx < N_NODES) {
            rowptr[idx] = run;
            cursor[idx] = run;
            run += __ldg(&counts[idx]);
        }
    }
    if (t == 1023) rowptr[N_NODES] = E_EDGES;
}

// ---------------------------------------------------------------------------
// place edges: 8 edges / thread, batched loads -> batched atomics -> stores
// ---------------------------------------------------------------------------
__global__ void place_kernel(const int* __restrict__ src, const int* __restrict__ dst,
                             int* __restrict__ cursor, int* __restrict__ esrc) {
    int base = (blockIdx.x * blockDim.x + threadIdx.x) * 8;
    if (base + 8 <= E_EDGES) {
        int d[8], s[8], pos[8];
        #pragma unroll
        for (int j = 0; j < 8; j++) d[j] = __ldg(&dst[base + j]);
        #pragma unroll
        for (int j = 0; j < 8; j++) s[j] = __ldg(&src[base + j]);
        #pragma unroll
        for (int j = 0; j < 8; j++) pos[j] = atomicAdd(&cursor[d[j]], 1);
        #pragma unroll
        for (int j = 0; j < 8; j++) esrc[pos[j]] = s[j];
    } else {
        for (int e = base; e < E_EDGES; e++) {
            int d = __ldg(&dst[e]);
            int p = atomicAdd(&cursor[d], 1);
            esrc[p] = __ldg(&src[e]);
        }
    }
}

// ---------------------------------------------------------------------------
// dual GEMM with packed f32x2 FMA:  p = in @ Wl    xr = in @ Wr + b
// block: 128 rows x 64 cols x 2 mats, 256 threads.
// thread: 8 rows (as 4 row-pairs in f32x2 lanes) x 4 cols x 2 mats.
// smem: sWl2/sWr2 = (w,w)-duplicated weights (ull [64][64]), sIn row-major.
// ---------------------------------------------------------------------------
__global__ __launch_bounds__(256) void dual_gemm_kernel(
        const float* __restrict__ in, const float* __restrict__ Wl,
        const float* __restrict__ Wr, const float* __restrict__ b,
        float* __restrict__ p, float* __restrict__ xr, int n) {
    extern __shared__ float sm[];
    unsigned long long* sWl2 = (unsigned long long*)sm;   // 4096 ull = 32 KB
    unsigned long long* sWr2 = sWl2 + 4096;               // 32 KB
    float* sIn = (float*)(sWr2 + 4096);                   // 128 x 68 = 34816 B
    __shared__ float sB[64];

    int tid = threadIdx.x;

    // duplicate-pack weights into smem: sW2[k][c] = (W[k][c], W[k][c])
    for (int i = tid; i < 1024; i += 256) {
        float4 wl = __ldg(&((const float4*)Wl)[i]);
        float4 wr = __ldg(&((const float4*)Wr)[i]);
        int k = i >> 4, c = (i & 15) * 4;
        F2U u;
        u.f = make_float2(wl.x, wl.x); sWl2[k * 64 + c + 0] = u.u;
        u.f = make_float2(wl.y, wl.y); sWl2[k * 64 + c + 1] = u.u;
        u.f = make_float2(wl.z, wl.z); sWl2[k * 64 + c + 2] = u.u;
        u.f = make_float2(wl.w, wl.w); sWl2[k * 64 + c + 3] = u.u;
        u.f = make_float2(wr.x, wr.x); sWr2[k * 64 + c + 0] = u.u;
        u.f = make_float2(wr.y, wr.y); sWr2[k * 64 + c + 1] = u.u;
        u.f = make_float2(wr.z, wr.z); sWr2[k * 64 + c + 2] = u.u;
        u.f = make_float2(wr.w, wr.w); sWr2[k * 64 + c + 3] = u.u;
    }
    if (tid < 64) sB[tid] = __ldg(&b[tid]);

    int row0 = blockIdx.x * 128;
    for (int i = tid; i < 2048; i += 256) {      // 128 rows x 16 float4
        int r = i >> 4, c4 = i & 15;
        float4 v = make_float4(0.f, 0.f, 0.f, 0.f);
        int gr = row0 + r;
        if (gr < n) v = __ldg(&((const float4*)in)[gr * 16 + c4]);
        *(float4*)&sIn[r * 68 + c4 * 4] = v;
    }
    __syncthreads();

    int tx = tid & 15, ty = tid >> 4;
    int cg = tx * 4;
    int r0 = ty * 8;

    unsigned long long accL[4][4], accR[4][4];   // [col j][rowpair rp]
    #pragma unroll
    for (int j = 0; j < 4; j++) {
        F2U ub; ub.f = make_float2(sB[cg + j], sB[cg + j]);
        #pragma unroll
        for (int rp = 0; rp < 4; rp++) { accL[j][rp] = 0ull; accR[j][rp] = ub.u; }
    }

    #pragma unroll 8
    for (int k = 0; k < 64; k++) {
        unsigned long long a[4];
        #pragma unroll
        for (int rp = 0; rp < 4; rp++) {
            F2U u;
            u.f = make_float2(sIn[(r0 + 2 * rp)     * 68 + k],
                              sIn[(r0 + 2 * rp + 1) * 68 + k]);
            a[rp] = u.u;
        }
        ulonglong2 wl01 = *(const ulonglong2*)&sWl2[k * 64 + cg];
        ulonglong2 wl23 = *(const ulonglong2*)&sWl2[k * 64 + cg + 2];
        ulonglong2 wr01 = *(const ulonglong2*)&sWr2[k * 64 + cg];
        ulonglong2 wr23 = *(const ulonglong2*)&sWr2[k * 64 + cg + 2];
        #pragma unroll
        for (int rp = 0; rp < 4; rp++) {
            FMA2(accL[0][rp], a[rp], wl01.x);
            FMA2(accL[1][rp], a[rp], wl01.y);
            FMA2(accL[2][rp], a[rp], wl23.x);
            FMA2(accL[3][rp], a[rp], wl23.y);
            FMA2(accR[0][rp], a[rp], wr01.x);
            FMA2(accR[1][rp], a[rp], wr01.y);
            FMA2(accR[2][rp], a[rp], wr23.x);
            FMA2(accR[3][rp], a[rp], wr23.y);
        }
    }

    #pragma unroll
    for (int rp = 0; rp < 4; rp++) {
        int gr = row0 + r0 + 2 * rp;
        F2U l0, l1, l2, l3, q0, q1, q2, q3;
        l0.u = accL[0][rp]; l1.u = accL[1][rp]; l2.u = accL[2][rp]; l3.u = accL[3][rp];
        q0.u = accR[0][rp]; q1.u = accR[1][rp]; q2.u = accR[2][rp]; q3.u = accR[3][rp];
        if (gr < n) {
            *(float4*)&p [gr * 64 + cg] = make_float4(l0.f.x, l1.f.x, l2.f.x, l3.f.x);
            *(float4*)&xr[gr * 64 + cg] = make_float4(q0.f.x, q1.f.x, q2.f.x, q3.f.x);
        }
        if (gr + 1 < n) {
            *(float4*)&p [(gr + 1) * 64 + cg] = make_float4(l0.f.y, l1.f.y, l2.f.y, l3.f.y);
            *(float4*)&xr[(gr + 1) * 64 + cg] = make_float4(q0.f.y, q1.f.y, q2.f.y, q3.f.y);
        }
    }
}

// ---------------------------------------------------------------------------
// fused aggregation + epilogue:
//   POOL=0:  out[node] = relu( segsum(p) + xr[node] )
//   POOL=1:  pool[batch[node]] += relu( segsum(p) + xr[node] )
// ---------------------------------------------------------------------------
template<int POOL>
__global__ __launch_bounds__(256) void agg_epi_kernel(
        const float* __restrict__ p,  const float* __restrict__ xr,
        const int* __restrict__ rowptr, const int* __restrict__ esrc,
        float* __restrict__ out, const int* __restrict__ batch,
        float* __restrict__ pool) {
    int node = (blockIdx.x * blockDim.x + threadIdx.x) >> 4;
    int lane = threadIdx.x & 15;
    if (node >= N_NODES) return;
    int beg = __ldg(&rowptr[node]);
    int end = __ldg(&rowptr[node + 1]);

    const float4* f4 = (const float4*)p;
    float4 a0 = make_float4(0.f, 0.f, 0.f, 0.f);
    float4 a1 = a0, a2 = a0, a3 = a0;

    int e = beg;
    for (; e + 3 < end; e += 4) {
        int s0 = __ldg(&esrc[e]);
        int s1 = __ldg(&esrc[e + 1]);
        int s2 = __ldg(&esrc[e + 2]);
        int s3 = __ldg(&esrc[e + 3]);
        float4 v0 = __ldg(&f4[s0 * 16 + lane]);
        float4 v1 = __ldg(&f4[s1 * 16 + lane]);
        float4 v2 = __ldg(&f4[s2 * 16 + lane]);
        float4 v3 = __ldg(&f4[s3 * 16 + lane]);
        a0.x += v0.x; a0.y += v0.y; a0.z += v0.z; a0.w += v0.w;
        a1.x += v1.x; a1.y += v1.y; a1.z += v1.z; a1.w += v1.w;
        a2.x += v2.x; a2.y += v2.y; a2.z += v2.z; a2.w += v2.w;
        a3.x += v3.x; a3.y += v3.y; a3.z += v3.z; a3.w += v3.w;
    }
    for (; e < end; e++) {
        int s0 = __ldg(&esrc[e]);
        float4 v0 = __ldg(&f4[s0 * 16 + lane]);
        a0.x += v0.x; a0.y += v0.y; a0.z += v0.z; a0.w += v0.w;
    }
    a0.x += a1.x + a2.x + a3.x;
    a0.y += a1.y + a2.y + a3.y;
    a0.z += a1.z + a2.z + a3.z;
    a0.w += a1.w + a2.w + a3.w;

    float4 r = __ldg(&((const float4*)xr)[node * 16 + lane]);
    float4 o;
    o.x = fmaxf(a0.x + r.x, 0.f);
    o.y = fmaxf(a0.y + r.y, 0.f);
    o.z = fmaxf(a0.z + r.z, 0.f);
    o.w = fmaxf(a0.w + r.w, 0.f);

    if (POOL) {
        int bg = __ldg(&batch[node]);
        float* pp = &pool[bg * 64 + lane * 4];
        asm volatile("red.global.add.v4.f32 [%0], {%1,%2,%3,%4};"
                     :: "l"(pp), "f"(o.x), "f"(o.y), "f"(o.z), "f"(o.w) : "memory");
    } else {
        ((float4*)out)[node * 16 + lane] = o;
    }
}

// ---------------------------------------------------------------------------
// head:  out = pool @ Wo + bo
// ---------------------------------------------------------------------------
__global__ void head_kernel(const float* __restrict__ pool,
                            const float* __restrict__ Wo,
                            const float* __restrict__ bo,
                            float*       __restrict__ out) {
    __shared__ float sW[64 * 16];
    __shared__ float sb[16];
    int tid = threadIdx.x;
    for (int i = tid; i < 64 * 16; i += 256) sW[i] = __ldg(&Wo[i]);
    if (tid < 16) sb[tid] = __ldg(&bo[tid]);
    __syncthreads();

    int t = blockIdx.x * blockDim.x + tid;
    if (t >= G_GRAPHS * O_DIM) return;
    int row = t >> 4;
    int col = t & 15;
    float acc = sb[col];
    const float* pr = &pool[row * 64];
    #pragma unroll
    for (int k = 0; k < 64; k++) acc += pr[k] * sW[k * 16 + col];
    out[row * O_DIM + col] = acc;
}

// ---------------------------------------------------------------------------
// launch
// ---------------------------------------------------------------------------
extern "C" void kernel_launch(void* const* d_in, const int* in_sizes, int n_in,
                              void* d_out, int out_size) {
    const float* x   = (const float*)d_in[0];
    const int*   ei  = (const int*)  d_in[1];
    const int*   bat = (const int*)  d_in[2];
    const float* Wl1 = (const float*)d_in[3];
    const float* Wr1 = (const float*)d_in[4];
    const float* b1  = (const float*)d_in[5];
    const float* Wl2 = (const float*)d_in[6];
    const float* Wr2 = (const float*)d_in[7];
    const float* b2  = (const float*)d_in[8];
    const float* Wo  = (const float*)d_in[9];
    const float* bo  = (const float*)d_in[10];
    float* out = (float*)d_out;

    const int* src = ei;
    const int* dst = ei + E_EDGES;

    float *p, *xr, *h1, *pool;
    int *counts, *rowptr, *cursor, *esrc;
    cudaGetSymbolAddress((void**)&p,      g_p);
    cudaGetSymbolAddress((void**)&xr,     g_xr);
    cudaGetSymbolAddress((void**)&h1,     g_h1);
    cudaGetSymbolAddress((void**)&pool,   g_pool);
    cudaGetSymbolAddress((void**)&counts, g_counts);
    cudaGetSymbolAddress((void**)&rowptr, g_rowptr);
    cudaGetSymbolAddress((void**)&cursor, g_cursor);
    cudaGetSymbolAddress((void**)&esrc,   g_esrc);

    static cudaStream_t s1 = nullptr;
    static cudaEvent_t evF = nullptr, evJ = nullptr;
    static bool attr_done = false;
    const int gemmSmem = 2 * 32768 + 128 * 68 * 4;   // 100,352 B
    if (!attr_done) {
        cudaFuncSetAttribute(dual_gemm_kernel,
                             cudaFuncAttributeMaxDynamicSharedMemorySize, gemmSmem);
        cudaStreamCreateWithFlags(&s1, cudaStreamNonBlocking);
        cudaEventCreateWithFlags(&evF, cudaEventDisableTiming);
        cudaEventCreateWithFlags(&evJ, cudaEventDisableTiming);
        attr_done = true;
    }

    const int e8Blocks  = (E_EDGES / 8 + 255) / 256;    // 489
    const int aggBlocks = (N_NODES * 16 + 255) / 256;   // 3125
    const int gemmBlocks = (N_NODES + 127) / 128;       // 391

    // fork: GEMM-1 (no graph dependency) runs concurrently with CSR build
    cudaEventRecord(evF, 0);
    cudaStreamWaitEvent(s1, evF, 0);

    // stream 0: CSR build + pool zero
    zero2_kernel<<<(N_NODES + 255) / 256, 256>>>(counts, pool);
    hist_kernel<<<e8Blocks, 256>>>(dst, counts);
    scan_kernel<<<1, 1024>>>(counts, rowptr, cursor);
    place_kernel<<<e8Blocks, 256>>>(src, dst, cursor, esrc);

    // stream 1: layer-1 projections  p = x@Wl1, xr = x@Wr1 + b1
    dual_gemm_kernel<<<gemmBlocks, 256, gemmSmem, s1>>>(x, Wl1, Wr1, b1, p, xr, N_NODES);
    cudaEventRecord(evJ, s1);
    cudaStreamWaitEvent(0, evJ, 0);

    // layer 1 aggregate + epilogue -> h1
    agg_epi_kernel<0><<<aggBlocks, 256>>>(p, xr, rowptr, esrc, h1, nullptr, nullptr);

    // layer 2 projections + aggregate (+ fused global add pool)
    dual_gemm_kernel<<<gemmBlocks, 256, gemmSmem>>>(h1, Wl2, Wr2, b2, p, xr, N_NODES);
    agg_epi_kernel<1><<<aggBlocks, 256>>>(p, xr, rowptr, esrc, nullptr, bat, pool);

    // head
    head_kernel<<<(G_GRAPHS * O_DIM + 255) / 256, 256>>>(pool, Wo, bo, out);
}

// round 6
// speedup vs baseline: 1.0723x; 1.0723x over previous
#include <cuda_runtime.h>
#include <cuda_bf16.h>

#define N_NODES 50000
#define E_EDGES 1000000
#define DIM     64
#define G_GRAPHS 512
#define O_DIM   16

// Scratch (__device__ globals; no allocation allowed)
__device__ float g_p   [N_NODES * DIM];     // projected (Wl) features
__device__ float g_xr  [N_NODES * DIM];     // root-path (Wr) features
__device__ float g_h1  [N_NODES * DIM];     // layer-1 output
__device__ float g_pool[G_GRAPHS * DIM];
__device__ int   g_counts[N_NODES];
__device__ int   g_rowptr[N_NODES + 1];
__device__ int   g_cursor[N_NODES];
__device__ int   g_esrc  [E_EDGES];

// ---------------------------------------------------------------------------
// zero counts + pool
// ---------------------------------------------------------------------------
__global__ void zero2_kernel(int* __restrict__ counts, float* __restrict__ pool) {
    int i = blockIdx.x * blockDim.x + threadIdx.x;
    if (i < N_NODES) counts[i] = 0;
    if (i < G_GRAPHS * DIM) pool[i] = 0.f;
}

// ---------------------------------------------------------------------------
// histogram of dst (1 edge / thread — max thread-level parallelism)
// ---------------------------------------------------------------------------
__global__ void hist_kernel(const int* __restrict__ dst, int* __restrict__ counts) {
    int e = blockIdx.x * blockDim.x + threadIdx.x;
    if (e < E_EDGES) atomicAdd(&counts[__ldg(&dst[e])], 1);
}

// ---------------------------------------------------------------------------
// exclusive scan of counts -> rowptr (+ cursor); warp-shuffle based
// ---------------------------------------------------------------------------
__global__ __launch_bounds__(1024) void scan_kernel(const int* __restrict__ counts,
                                                    int* __restrict__ rowptr,
                                                    int* __restrict__ cursor) {
    __shared__ int warpsum[32];
    const int CH = 49;
    int t = threadIdx.x;
    int base = t * CH;
    int lane = t & 31, wid = t >> 5;

    int s = 0;
    #pragma unroll 7
    for (int i = 0; i < CH; i++) {
        int idx = base + i;
        if (idx < N_NODES) s += __ldg(&counts[idx]);
    }
    int v = s;
    #pragma unroll
    for (int off = 1; off < 32; off <<= 1) {
        int u = __shfl_up_sync(0xffffffffu, v, off);
        if (lane >= off) v += u;
    }
    if (lane == 31) warpsum[wid] = v;
    __syncthreads();
    if (wid == 0) {
        int w = warpsum[lane];
        #pragma unroll
        for (int off = 1; off < 32; off <<= 1) {
            int u = __shfl_up_sync(0xffffffffu, w, off);
            if (lane >= off) w += u;
        }
        warpsum[lane] = w;
    }
    __syncthreads();

    int run = v - s + (wid > 0 ? warpsum[wid - 1] : 0);
    #pragma unroll 7
    for (int i = 0; i < CH; i++) {
        int idx = base + i;
        if (idx < N_NODES) {
            rowptr[idx] = run;
            cursor[idx] = run;
            run += __ldg(&counts[idx]);
        }
    }
    if (t == 1023) rowptr[N_NODES] = E_EDGES;
}

// ---------------------------------------------------------------------------
// place edges into dst-sorted order (1 edge / thread — best measured: 17.3us)
// ---------------------------------------------------------------------------
__global__ void place_kernel(const int* __restrict__ src, const int* __restrict__ dst,
                             int* __restrict__ cursor, int* __restrict__ esrc) {
    int e = blockIdx.x * blockDim.x + threadIdx.x;
    if (e >= E_EDGES) return;
    int d = __ldg(&dst[e]);
    int p = atomicAdd(&cursor[d], 1);
    esrc[p] = __ldg(&src[e]);
}

// ---------------------------------------------------------------------------
// dual GEMM (R4-proven scalar version):  p = in @ Wl    xr = in @ Wr + b
// block: 128 rows x 64 cols, 256 threads, thread tile 8 rows x 4 cols x 2 mats
// ---------------------------------------------------------------------------
__global__ __launch_bounds__(256) void dual_gemm_kernel(
        const float* __restrict__ in, const float* __restrict__ Wl,
        const float* __restrict__ Wr, const float* __restrict__ b,
        float* __restrict__ p, float* __restrict__ xr, int n) {
    extern __shared__ float sm[];
    float* sIn = sm;                    // 128 * 68
    float* sWl = sm + 128 * 68;         // 64 * 64
    float* sWr = sWl + 4096;            // 64 * 64
    __shared__ float sB[64];

    int tid = threadIdx.x;
    for (int i = tid; i < 1024; i += 256) {
        ((float4*)sWl)[i] = __ldg(&((const float4*)Wl)[i]);
        ((float4*)sWr)[i] = __ldg(&((const float4*)Wr)[i]);
    }
    if (tid < 64) sB[tid] = __ldg(&b[tid]);

    int row0 = blockIdx.x * 128;
    for (int i = tid; i < 2048; i += 256) {      // 128 rows x 16 float4
        int r = i >> 4, c4 = i & 15;
        float4 v = make_float4(0.f, 0.f, 0.f, 0.f);
        int gr = row0 + r;
        if (gr < n) v = __ldg(&((const float4*)in)[gr * 16 + c4]);
        *(float4*)&sIn[r * 68 + c4 * 4] = v;
    }
    __syncthreads();

    int tx = tid & 15, ty = tid >> 4;
    int cg = tx * 4;

    float accL[8][4], accR[8][4];
    #pragma unroll
    for (int i = 0; i < 8; i++) {
        #pragma unroll
        for (int j = 0; j < 4; j++) { accL[i][j] = 0.f; accR[i][j] = sB[cg + j]; }
    }

    #pragma unroll 8
    for (int k = 0; k < 64; k++) {
        float4 wl = *(const float4*)&sWl[k * 64 + cg];
        float4 wr = *(const float4*)&sWr[k * 64 + cg];
        #pragma unroll
        for (int i = 0; i < 8; i++) {
            float a = sIn[(ty + 16 * i) * 68 + k];
            accL[i][0] += a * wl.x; accL[i][1] += a * wl.y;
            accL[i][2] += a * wl.z; accL[i][3] += a * wl.w;
            accR[i][0] += a * wr.x; accR[i][1] += a * wr.y;
            accR[i][2] += a * wr.z; accR[i][3] += a * wr.w;
        }
    }

    #pragma unroll
    for (int i = 0; i < 8; i++) {
        int gr = row0 + ty + 16 * i;
        if (gr < n) {
            *(float4*)&p [gr * 64 + cg] = *(float4*)accL[i];
            *(float4*)&xr[gr * 64 + cg] = *(float4*)accR[i];
        }
    }
}

// ---------------------------------------------------------------------------
// fused aggregation + epilogue, 8 edges in flight:
//   POOL=0:  out[node] = relu( segsum(p) + xr[node] )
//   POOL=1:  pool[batch[node]] += relu( segsum(p) + xr[node] )
// ---------------------------------------------------------------------------
template<int POOL>
__global__ __launch_bounds__(256) void agg_epi_kernel(
        const float* __restrict__ p,  const float* __restrict__ xr,
        const int* __restrict__ rowptr, const int* __restrict__ esrc,
        float* __restrict__ out, const int* __restrict__ batch,
        float* __restrict__ pool) {
    int node = (blockIdx.x * blockDim.x + threadIdx.x) >> 4;
    int lane = threadIdx.x & 15;
    if (node >= N_NODES) return;
    int beg = __ldg(&rowptr[node]);
    int end = __ldg(&rowptr[node + 1]);

    const float4* f4 = (const float4*)p;
    float4 a0 = make_float4(0.f, 0.f, 0.f, 0.f);
    float4 a1 = a0, a2 = a0, a3 = a0;

    int e = beg;
    // 8 edges in flight: 8 independent LDG.128, pairwise-accumulated into 4 regs
    for (; e + 7 < end; e += 8) {
        int s0 = __ldg(&esrc[e]);
        int s1 = __ldg(&esrc[e + 1]);
        int s2 = __ldg(&esrc[e + 2]);
        int s3 = __ldg(&esrc[e + 3]);
        int s4 = __ldg(&esrc[e + 4]);
        int s5 = __ldg(&esrc[e + 5]);
        int s6 = __ldg(&esrc[e + 6]);
        int s7 = __ldg(&esrc[e + 7]);
        float4 v0 = __ldg(&f4[s0 * 16 + lane]);
        float4 v1 = __ldg(&f4[s1 * 16 + lane]);
        float4 v2 = __ldg(&f4[s2 * 16 + lane]);
        float4 v3 = __ldg(&f4[s3 * 16 + lane]);
        float4 v4 = __ldg(&f4[s4 * 16 + lane]);
        float4 v5 = __ldg(&f4[s5 * 16 + lane]);
        float4 v6 = __ldg(&f4[s6 * 16 + lane]);
        float4 v7 = __ldg(&f4[s7 * 16 + lane]);
        a0.x += v0.x + v4.x; a0.y += v0.y + v4.y; a0.z += v0.z + v4.z; a0.w += v0.w + v4.w;
        a1.x += v1.x + v5.x; a1.y += v1.y + v5.y; a1.z += v1.z + v5.z; a1.w += v1.w + v5.w;
        a2.x += v2.x + v6.x; a2.y += v2.y + v6.y; a2.z += v2.z + v6.z; a2.w += v2.w + v6.w;
        a3.x += v3.x + v7.x; a3.y += v3.y + v7.y; a3.z += v3.z + v7.z; a3.w += v3.w + v7.w;
    }
    for (; e + 3 < end; e += 4) {
        int s0 = __ldg(&esrc[e]);
        int s1 = __ldg(&esrc[e + 1]);
        int s2 = __ldg(&esrc[e + 2]);
        int s3 = __ldg(&esrc[e + 3]);
        float4 v0 = __ldg(&f4[s0 * 16 + lane]);
        float4 v1 = __ldg(&f4[s1 * 16 + lane]);
        float4 v2 = __ldg(&f4[s2 * 16 + lane]);
        float4 v3 = __ldg(&f4[s3 * 16 + lane]);
        a0.x += v0.x; a0.y += v0.y; a0.z += v0.z; a0.w += v0.w;
        a1.x += v1.x; a1.y += v1.y; a1.z += v1.z; a1.w += v1.w;
        a2.x += v2.x; a2.y += v2.y; a2.z += v2.z; a2.w += v2.w;
        a3.x += v3.x; a3.y += v3.y; a3.z += v3.z; a3.w += v3.w;
    }
    for (; e < end; e++) {
        int s0 = __ldg(&esrc[e]);
        float4 v0 = __ldg(&f4[s0 * 16 + lane]);
        a0.x += v0.x; a0.y += v0.y; a0.z += v0.z; a0.w += v0.w;
    }
    a0.x += a1.x + a2.x + a3.x;
    a0.y += a1.y + a2.y + a3.y;
    a0.z += a1.z + a2.z + a3.z;
    a0.w += a1.w + a2.w + a3.w;

    float4 r = __ldg(&((const float4*)xr)[node * 16 + lane]);
    float4 o;
    o.x = fmaxf(a0.x + r.x, 0.f);
    o.y = fmaxf(a0.y + r.y, 0.f);
    o.z = fmaxf(a0.z + r.z, 0.f);
    o.w = fmaxf(a0.w + r.w, 0.f);

    if (POOL) {
        int bg = __ldg(&batch[node]);
        float* pp = &pool[bg * 64 + lane * 4];
        asm volatile("red.global.add.v4.f32 [%0], {%1,%2,%3,%4};"
                     :: "l"(pp), "f"(o.x), "f"(o.y), "f"(o.z), "f"(o.w) : "memory");
    } else {
        ((float4*)out)[node * 16 + lane] = o;
    }
}

// ---------------------------------------------------------------------------
// head:  out = pool @ Wo + bo
// ---------------------------------------------------------------------------
__global__ void head_kernel(const float* __restrict__ pool,
                            const float* __restrict__ Wo,
                            const float* __restrict__ bo,
                            float*       __restrict__ out) {
    __shared__ float sW[64 * 16];
    __shared__ float sb[16];
    int tid = threadIdx.x;
    for (int i = tid; i < 64 * 16; i += 256) sW[i] = __ldg(&Wo[i]);
    if (tid < 16) sb[tid] = __ldg(&bo[tid]);
    __syncthreads();

    int t = blockIdx.x * blockDim.x + tid;
    if (t >= G_GRAPHS * O_DIM) return;
    int row = t >> 4;
    int col = t & 15;
    float acc = sb[col];
    const float* pr = &pool[row * 64];
    #pragma unroll
    for (int k = 0; k < 64; k++) acc += pr[k] * sW[k * 16 + col];
    out[row * O_DIM + col] = acc;
}

// ---------------------------------------------------------------------------
// launch
// ---------------------------------------------------------------------------
extern "C" void kernel_launch(void* const* d_in, const int* in_sizes, int n_in,
                              void* d_out, int out_size) {
    const float* x   = (const float*)d_in[0];
    const int*   ei  = (const int*)  d_in[1];
    const int*   bat = (const int*)  d_in[2];
    const float* Wl1 = (const float*)d_in[3];
    const float* Wr1 = (const float*)d_in[4];
    const float* b1  = (const float*)d_in[5];
    const float* Wl2 = (const float*)d_in[6];
    const float* Wr2 = (const float*)d_in[7];
    const float* b2  = (const float*)d_in[8];
    const float* Wo  = (const float*)d_in[9];
    const float* bo  = (const float*)d_in[10];
    float* out = (float*)d_out;

    const int* src = ei;
    const int* dst = ei + E_EDGES;

    float *p, *xr, *h1, *pool;
    int *counts, *rowptr, *cursor, *esrc;
    cudaGetSymbolAddress((void**)&p,      g_p);
    cudaGetSymbolAddress((void**)&xr,     g_xr);
    cudaGetSymbolAddress((void**)&h1,     g_h1);
    cudaGetSymbolAddress((void**)&pool,   g_pool);
    cudaGetSymbolAddress((void**)&counts, g_counts);
    cudaGetSymbolAddress((void**)&rowptr, g_rowptr);
    cudaGetSymbolAddress((void**)&cursor, g_cursor);
    cudaGetSymbolAddress((void**)&esrc,   g_esrc);

    static cudaStream_t s1 = nullptr;
    static cudaEvent_t evF = nullptr, evJ = nullptr;
    static bool attr_done = false;
    const int gemmSmem = (128 * 68 + 2 * 4096) * sizeof(float);   // 67,584 B
    if (!attr_done) {
        cudaFuncSetAttribute(dual_gemm_kernel,
                             cudaFuncAttributeMaxDynamicSharedMemorySize, gemmSmem);
        cudaStreamCreateWithFlags(&s1, cudaStreamNonBlocking);
        cudaEventCreateWithFlags(&evF, cudaEventDisableTiming);
        cudaEventCreateWithFlags(&evJ, cudaEventDisableTiming);
        attr_done = true;
    }

    const int eBlocks   = (E_EDGES + 255) / 256;        // 3907
    const int aggBlocks = (N_NODES * 16 + 255) / 256;   // 3125
    const int gemmBlocks = (N_NODES + 127) / 128;       // 391

    // fork: GEMM-1 (no graph dependency) runs concurrently with CSR build
    cudaEventRecord(evF, 0);
    cudaStreamWaitEvent(s1, evF, 0);

    // stream 0: CSR build + pool zero
    zero2_kernel<<<(N_NODES + 255) / 256, 256>>>(counts, pool);
    hist_kernel<<<eBlocks, 256>>>(dst, counts);
    scan_kernel<<<1, 1024>>>(counts, rowptr, cursor);
    place_kernel<<<eBlocks, 256>>>(src, dst, cursor, esrc);

    // stream 1: layer-1 projections  p = x@Wl1, xr = x@Wr1 + b1
    dual_gemm_kernel<<<gemmBlocks, 256, gemmSmem, s1>>>(x, Wl1, Wr1, b1, p, xr, N_NODES);
    cudaEventRecord(evJ, s1);
    cudaStreamWaitEvent(0, evJ, 0);

    // layer 1 aggregate + epilogue -> h1
    agg_epi_kernel<0><<<aggBlocks, 256>>>(p, xr, rowptr, esrc, h1, nullptr, nullptr);

    // layer 2 projections + aggregate (+ fused global add pool)
    dual_gemm_kernel<<<gemmBlocks, 256, gemmSmem>>>(h1, Wl2, Wr2, b2, p, xr, N_NODES);
    agg_epi_kernel<1><<<aggBlocks, 256>>>(p, xr, rowptr, esrc, nullptr, bat, pool);

    // head
    head_kernel<<<(G_GRAPHS * O_DIM + 255) / 256, 256>>>(pool, Wo, bo, out);
}

// round 7
// speedup vs baseline: 1.1489x; 1.0715x over previous
#include <cuda_runtime.h>
#include <cuda_fp16.h>
#include <cuda_bf16.h>

#define N_NODES 50000
#define E_EDGES 1000000
#define DIM     64
#define G_GRAPHS 512
#define O_DIM   16

// Scratch (__device__ globals; no allocation allowed)
__device__ __half g_p [N_NODES * DIM];      // projected (Wl) features, fp16 (6.4 MB)
__device__ float g_xr  [N_NODES * DIM];     // root-path (Wr) features
__device__ float g_h1  [N_NODES * DIM];     // layer-1 output
__device__ float g_pool[G_GRAPHS * DIM];
__device__ int   g_counts[N_NODES];
__device__ int   g_rowptr[N_NODES + 1];
__device__ int   g_cursor[N_NODES];
__device__ int   g_esrc  [E_EDGES];

// ---------------------------------------------------------------------------
// zero counts + pool
// ---------------------------------------------------------------------------
__global__ void zero2_kernel(int* __restrict__ counts, float* __restrict__ pool) {
    int i = blockIdx.x * blockDim.x + threadIdx.x;
    if (i < N_NODES) counts[i] = 0;
    if (i < G_GRAPHS * DIM) pool[i] = 0.f;
}

// ---------------------------------------------------------------------------
// histogram of dst (1 edge / thread — max thread-level parallelism)
// ---------------------------------------------------------------------------
__global__ void hist_kernel(const int* __restrict__ dst, int* __restrict__ counts) {
    int e = blockIdx.x * blockDim.x + threadIdx.x;
    if (e < E_EDGES) atomicAdd(&counts[__ldg(&dst[e])], 1);
}

// ---------------------------------------------------------------------------
// exclusive scan of counts -> rowptr (+ cursor); warp-shuffle based
// ---------------------------------------------------------------------------
__global__ __launch_bounds__(1024) void scan_kernel(const int* __restrict__ counts,
                                                    int* __restrict__ rowptr,
                                                    int* __restrict__ cursor) {
    __shared__ int warpsum[32];
    const int CH = 49;
    int t = threadIdx.x;
    int base = t * CH;
    int lane = t & 31, wid = t >> 5;

    int s = 0;
    #pragma unroll 7
    for (int i = 0; i < CH; i++) {
        int idx = base + i;
        if (idx < N_NODES) s += __ldg(&counts[idx]);
    }
    int v = s;
    #pragma unroll
    for (int off = 1; off < 32; off <<= 1) {
        int u = __shfl_up_sync(0xffffffffu, v, off);
        if (lane >= off) v += u;
    }
    if (lane == 31) warpsum[wid] = v;
    __syncthreads();
    if (wid == 0) {
        int w = warpsum[lane];
        #pragma unroll
        for (int off = 1; off < 32; off <<= 1) {
            int u = __shfl_up_sync(0xffffffffu, w, off);
            if (lane >= off) w += u;
        }
        warpsum[lane] = w;
    }
    __syncthreads();

    int run = v - s + (wid > 0 ? warpsum[wid - 1] : 0);
    #pragma unroll 7
    for (int i = 0; i < CH; i++) {
        int idx = base + i;
        if (idx < N_NODES) {
            rowptr[idx] = run;
            cursor[idx] = run;
            run += __ldg(&counts[idx]);
        }
    }
    if (t == 1023) rowptr[N_NODES] = E_EDGES;
}

// ---------------------------------------------------------------------------
// place edges into dst-sorted order (1 edge / thread — best measured)
// ---------------------------------------------------------------------------
__global__ void place_kernel(const int* __restrict__ src, const int* __restrict__ dst,
                             int* __restrict__ cursor, int* __restrict__ esrc) {
    int e = blockIdx.x * blockDim.x + threadIdx.x;
    if (e >= E_EDGES) return;
    int d = __ldg(&dst[e]);
    int p = atomicAdd(&cursor[d], 1);
    esrc[p] = __ldg(&src[e]);
}

// ---------------------------------------------------------------------------
// dual GEMM:  p(fp16) = in @ Wl    xr(fp32) = in @ Wr + b
// block: 128 rows x 64 cols, 256 threads, thread tile 8 rows x 4 cols x 2 mats
// ---------------------------------------------------------------------------
__global__ __launch_bounds__(256) void dual_gemm_kernel(
        const float* __restrict__ in, const float* __restrict__ Wl,
        const float* __restrict__ Wr, const float* __restrict__ b,
        __half* __restrict__ p, float* __restrict__ xr, int n) {
    extern __shared__ float sm[];
    float* sIn = sm;                    // 128 * 68
    float* sWl = sm + 128 * 68;         // 64 * 64
    float* sWr = sWl + 4096;            // 64 * 64
    __shared__ float sB[64];

    int tid = threadIdx.x;
    for (int i = tid; i < 1024; i += 256) {
        ((float4*)sWl)[i] = __ldg(&((const float4*)Wl)[i]);
        ((float4*)sWr)[i] = __ldg(&((const float4*)Wr)[i]);
    }
    if (tid < 64) sB[tid] = __ldg(&b[tid]);

    int row0 = blockIdx.x * 128;
    for (int i = tid; i < 2048; i += 256) {      // 128 rows x 16 float4
        int r = i >> 4, c4 = i & 15;
        float4 v = make_float4(0.f, 0.f, 0.f, 0.f);
        int gr = row0 + r;
        if (gr < n) v = __ldg(&((const float4*)in)[gr * 16 + c4]);
        *(float4*)&sIn[r * 68 + c4 * 4] = v;
    }
    __syncthreads();

    int tx = tid & 15, ty = tid >> 4;
    int cg = tx * 4;

    float accL[8][4], accR[8][4];
    #pragma unroll
    for (int i = 0; i < 8; i++) {
        #pragma unroll
        for (int j = 0; j < 4; j++) { accL[i][j] = 0.f; accR[i][j] = sB[cg + j]; }
    }

    #pragma unroll 8
    for (int k = 0; k < 64; k++) {
        float4 wl = *(const float4*)&sWl[k * 64 + cg];
        float4 wr = *(const float4*)&sWr[k * 64 + cg];
        #pragma unroll
        for (int i = 0; i < 8; i++) {
            float a = sIn[(ty + 16 * i) * 68 + k];
            accL[i][0] += a * wl.x; accL[i][1] += a * wl.y;
            accL[i][2] += a * wl.z; accL[i][3] += a * wl.w;
            accR[i][0] += a * wr.x; accR[i][1] += a * wr.y;
            accR[i][2] += a * wr.z; accR[i][3] += a * wr.w;
        }
    }

    #pragma unroll
    for (int i = 0; i < 8; i++) {
        int gr = row0 + ty + 16 * i;
        if (gr < n) {
            // p: 4 consecutive cols as two half2 (8-byte store)
            __half2 h01 = __floats2half2_rn(accL[i][0], accL[i][1]);
            __half2 h23 = __floats2half2_rn(accL[i][2], accL[i][3]);
            uint2 hp;
            hp.x = *(unsigned int*)&h01;
            hp.y = *(unsigned int*)&h23;
            *(uint2*)&p[gr * 64 + cg] = hp;
            *(float4*)&xr[gr * 64 + cg] = *(float4*)accR[i];
        }
    }
}

// ---------------------------------------------------------------------------
// fused aggregation + epilogue (fp16 gather, fp32 accumulate):
//   POOL=0:  out[node] = relu( segsum(p) + xr[node] )
//   POOL=1:  pool[batch[node]] += relu( segsum(p) + xr[node] )
// 8 lanes per node; each lane loads 8 halves (uint4 = 16B) per edge.
// Edge pairs combined with __hadd2 (one fp16 add), then fp32 accumulate.
// ---------------------------------------------------------------------------
template<int POOL>
__global__ __launch_bounds__(256) void agg_epi_kernel(
        const __half* __restrict__ p,  const float* __restrict__ xr,
        const int* __restrict__ rowptr, const int* __restrict__ esrc,
        float* __restrict__ out, const int* __restrict__ batch,
        float* __restrict__ pool) {
    int node = (blockIdx.x * blockDim.x + threadIdx.x) >> 3;
    int lane = threadIdx.x & 7;
    if (node >= N_NODES) return;
    int beg = __ldg(&rowptr[node]);
    int end = __ldg(&rowptr[node + 1]);

    const uint4* f = (const uint4*)p;    // row = 8 uint4 (64 halves)

    float2 a0 = make_float2(0.f, 0.f);
    float2 a1 = a0, a2 = a0, a3 = a0;

    #define ACC_PAIR(u, v) do {                                              \
        __half2 w0 = __hadd2(*(__half2*)&(u).x, *(__half2*)&(v).x);          \
        __half2 w1 = __hadd2(*(__half2*)&(u).y, *(__half2*)&(v).y);          \
        __half2 w2 = __hadd2(*(__half2*)&(u).z, *(__half2*)&(v).z);          \
        __half2 w3 = __hadd2(*(__half2*)&(u).w, *(__half2*)&(v).w);          \
        float2 f0 = __half22float2(w0); a0.x += f0.x; a0.y += f0.y;          \
        float2 f1 = __half22float2(w1); a1.x += f1.x; a1.y += f1.y;          \
        float2 f2 = __half22float2(w2); a2.x += f2.x; a2.y += f2.y;          \
        float2 f3 = __half22float2(w3); a3.x += f3.x; a3.y += f3.y;          \
    } while (0)

    #define ACC_ONE(u) do {                                                  \
        float2 f0 = __half22float2(*(__half2*)&(u).x); a0.x += f0.x; a0.y += f0.y; \
        float2 f1 = __half22float2(*(__half2*)&(u).y); a1.x += f1.x; a1.y += f1.y; \
        float2 f2 = __half22float2(*(__half2*)&(u).z); a2.x += f2.x; a2.y += f2.y; \
        float2 f3 = __half22float2(*(__half2*)&(u).w); a3.x += f3.x; a3.y += f3.y; \
    } while (0)

    int e = beg;
    // 8 edges in flight (8 independent LDG.128)
    for (; e + 7 < end; e += 8) {
        int s0 = __ldg(&esrc[e]);
        int s1 = __ldg(&esrc[e + 1]);
        int s2 = __ldg(&esrc[e + 2]);
        int s3 = __ldg(&esrc[e + 3]);
        int s4 = __ldg(&esrc[e + 4]);
        int s5 = __ldg(&esrc[e + 5]);
        int s6 = __ldg(&esrc[e + 6]);
        int s7 = __ldg(&esrc[e + 7]);
        uint4 v0 = __ldg(&f[s0 * 8 + lane]);
        uint4 v1 = __ldg(&f[s1 * 8 + lane]);
        uint4 v2 = __ldg(&f[s2 * 8 + lane]);
        uint4 v3 = __ldg(&f[s3 * 8 + lane]);
        uint4 v4 = __ldg(&f[s4 * 8 + lane]);
        uint4 v5 = __ldg(&f[s5 * 8 + lane]);
        uint4 v6 = __ldg(&f[s6 * 8 + lane]);
        uint4 v7 = __ldg(&f[s7 * 8 + lane]);
        ACC_PAIR(v0, v1);
        ACC_PAIR(v2, v3);
        ACC_PAIR(v4, v5);
        ACC_PAIR(v6, v7);
    }
    for (; e + 1 < end; e += 2) {
        int s0 = __ldg(&esrc[e]);
        int s1 = __ldg(&esrc[e + 1]);
        uint4 v0 = __ldg(&f[s0 * 8 + lane]);
        uint4 v1 = __ldg(&f[s1 * 8 + lane]);
        ACC_PAIR(v0, v1);
    }
    if (e < end) {
        int s0 = __ldg(&esrc[e]);
        uint4 v0 = __ldg(&f[s0 * 8 + lane]);
        ACC_ONE(v0);
    }

    // epilogue: 8 output cols = lane*8 .. lane*8+7
    const float4* xr4 = (const float4*)xr;
    float4 r0 = __ldg(&xr4[node * 16 + lane * 2]);
    float4 r1 = __ldg(&xr4[node * 16 + lane * 2 + 1]);
    float4 o0, o1;
    o0.x = fmaxf(a0.x + r0.x, 0.f);
    o0.y = fmaxf(a0.y + r0.y, 0.f);
    o0.z = fmaxf(a1.x + r0.z, 0.f);
    o0.w = fmaxf(a1.y + r0.w, 0.f);
    o1.x = fmaxf(a2.x + r1.x, 0.f);
    o1.y = fmaxf(a2.y + r1.y, 0.f);
    o1.z = fmaxf(a3.x + r1.z, 0.f);
    o1.w = fmaxf(a3.y + r1.w, 0.f);

    if (POOL) {
        int bg = __ldg(&batch[node]);
        float* pp = &pool[bg * 64 + lane * 8];
        asm volatile("red.global.add.v4.f32 [%0], {%1,%2,%3,%4};"
                     :: "l"(pp), "f"(o0.x), "f"(o0.y), "f"(o0.z), "f"(o0.w) : "memory");
        asm volatile("red.global.add.v4.f32 [%0], {%1,%2,%3,%4};"
                     :: "l"(pp + 4), "f"(o1.x), "f"(o1.y), "f"(o1.z), "f"(o1.w) : "memory");
    } else {
        float4* op = (float4*)&out[node * 64 + lane * 8];
        op[0] = o0;
        op[1] = o1;
    }
    #undef ACC_PAIR
    #undef ACC_ONE
}

// ---------------------------------------------------------------------------
// head:  out = pool @ Wo + bo
// ---------------------------------------------------------------------------
__global__ void head_kernel(const float* __restrict__ pool,
                            const float* __restrict__ Wo,
                            const float* __restrict__ bo,
                            float*       __restrict__ out) {
    __shared__ float sW[64 * 16];
    __shared__ float sb[16];
    int tid = threadIdx.x;
    for (int i = tid; i < 64 * 16; i += 256) sW[i] = __ldg(&Wo[i]);
    if (tid < 16) sb[tid] = __ldg(&bo[tid]);
    __syncthreads();

    int t = blockIdx.x * blockDim.x + tid;
    if (t >= G_GRAPHS * O_DIM) return;
    int row = t >> 4;
    int col = t & 15;
    float acc = sb[col];
    const float* pr = &pool[row * 64];
    #pragma unroll
    for (int k = 0; k < 64; k++) acc += pr[k] * sW[k * 16 + col];
    out[row * O_DIM + col] = acc;
}

// ---------------------------------------------------------------------------
// launch
// ---------------------------------------------------------------------------
extern "C" void kernel_launch(void* const* d_in, const int* in_sizes, int n_in,
                              void* d_out, int out_size) {
    const float* x   = (const float*)d_in[0];
    const int*   ei  = (const int*)  d_in[1];
    const int*   bat = (const int*)  d_in[2];
    const float* Wl1 = (const float*)d_in[3];
    const float* Wr1 = (const float*)d_in[4];
    const float* b1  = (const float*)d_in[5];
    const float* Wl2 = (const float*)d_in[6];
    const float* Wr2 = (const float*)d_in[7];
    const float* b2  = (const float*)d_in[8];
    const float* Wo  = (const float*)d_in[9];
    const float* bo  = (const float*)d_in[10];
    float* out = (float*)d_out;

    const int* src = ei;
    const int* dst = ei + E_EDGES;

    __half* p;
    float *xr, *h1, *pool;
    int *counts, *rowptr, *cursor, *esrc;
    cudaGetSymbolAddress((void**)&p,      g_p);
    cudaGetSymbolAddress((void**)&xr,     g_xr);
    cudaGetSymbolAddress((void**)&h1,     g_h1);
    cudaGetSymbolAddress((void**)&pool,   g_pool);
    cudaGetSymbolAddress((void**)&counts, g_counts);
    cudaGetSymbolAddress((void**)&rowptr, g_rowptr);
    cudaGetSymbolAddress((void**)&cursor, g_cursor);
    cudaGetSymbolAddress((void**)&esrc,   g_esrc);

    static cudaStream_t s1 = nullptr;
    static cudaEvent_t evF = nullptr, evJ = nullptr;
    static bool attr_done = false;
    const int gemmSmem = (128 * 68 + 2 * 4096) * sizeof(float);   // 67,584 B
    if (!attr_done) {
        cudaFuncSetAttribute(dual_gemm_kernel,
                             cudaFuncAttributeMaxDynamicSharedMemorySize, gemmSmem);
        cudaStreamCreateWithFlags(&s1, cudaStreamNonBlocking);
        cudaEventCreateWithFlags(&evF, cudaEventDisableTiming);
        cudaEventCreateWithFlags(&evJ, cudaEventDisableTiming);
        attr_done = true;
    }

    const int eBlocks   = (E_EDGES + 255) / 256;        // 3907
    const int aggBlocks = (N_NODES * 8 + 255) / 256;    // 1563
    const int gemmBlocks = (N_NODES + 127) / 128;       // 391

    // fork: GEMM-1 (no graph dependency) runs concurrently with CSR build
    cudaEventRecord(evF, 0);
    cudaStreamWaitEvent(s1, evF, 0);

    // stream 0: CSR build + pool zero
    zero2_kernel<<<(N_NODES + 255) / 256, 256>>>(counts, pool);
    hist_kernel<<<eBlocks, 256>>>(dst, counts);
    scan_kernel<<<1, 1024>>>(counts, rowptr, cursor);
    place_kernel<<<eBlocks, 256>>>(src, dst, cursor, esrc);

    // stream 1: layer-1 projections  p = x@Wl1 (fp16), xr = x@Wr1 + b1
    dual_gemm_kernel<<<gemmBlocks, 256, gemmSmem, s1>>>(x, Wl1, Wr1, b1, p, xr, N_NODES);
    cudaEventRecord(evJ, s1);
    cudaStreamWaitEvent(0, evJ, 0);

    // layer 1 aggregate + epilogue -> h1
    agg_epi_kernel<0><<<aggBlocks, 256>>>(p, xr, rowptr, esrc, h1, nullptr, nullptr);

    // layer 2 projections + aggregate (+ fused global add pool)
    dual_gemm_kernel<<<gemmBlocks, 256, gemmSmem>>>(h1, Wl2, Wr2, b2, p, xr, N_NODES);
    agg_epi_kernel<1><<<aggBlocks, 256>>>(p, xr, rowptr, esrc, nullptr, bat, pool);

    // head
    head_kernel<<<(G_GRAPHS * O_DIM + 255) / 256, 256>>>(pool, Wo, bo, out);
}